// round 10
// baseline (speedup 1.0000x reference)
#include <cuda_runtime.h>
#include <cuda_fp16.h>
#include <cstdint>

// ============================================================================
// RetinaNet heads: pure fp16 implicit GEMM via mma.sync (HMMA) on sm_103.
// Round 10: double-buffered A tile (removes the warp-pair barrier and takes
// the convert+STS chain off the critical path), A build streamed through the
// MMA k-loop (LDG at ks0/ks2, convert+STS at ks1/ks3). One __syncthreads per
// stage. B cp.async double-buffer issued a full stage ahead (unchanged).
// ============================================================================

#define NTH 256
#define C_IN 256
#define APW_TOTAL 32760
#define REG_STRIDE_N (4 * APW_TOTAL)
#define CLS_STRIDE_N (9 * APW_TOTAL)
#define CONF_BASE (16 * 4 * APW_TOTAL)

#define LDK 72                        // smem row stride in halves (144 B)
#define A_ONE (128 * LDK * 2)         // 18432 B per A buffer
#define A_BYTES (2 * A_ONE)           // double-buffered A
#define B_STAGE_B (80 * LDK * 2)      // 11520 B per B stage
#define B_OFF A_BYTES
#define SMEM_TOTAL (A_BYTES + 2 * B_STAGE_B)   // 59904

// B pack: [head 2][stage 36][n 80][k 72] halves (stage = tap*4+kc)
#define BPACK_TILE (80 * LDK)
#define BPACK_ELEMS (2 * 36 * BPACK_TILE)
__device__ __align__(16) __half g_bpack[BPACK_ELEMS];
__device__ float g_bias[2 * 80];

// ---------------------------------------------------------------------------
__device__ __forceinline__ uint32_t smem_u32(const void* p) {
    uint32_t a;
    asm("{ .reg .u64 t; cvta.to.shared.u64 t, %1; cvt.u32.u64 %0, t; }" : "=r"(a) : "l"(p));
    return a;
}
__device__ __forceinline__ void cp_async16(uint32_t dst, const void* src) {
    asm volatile("cp.async.cg.shared.global [%0], [%1], 16;" :: "r"(dst), "l"(src));
}
#define CP_COMMIT() asm volatile("cp.async.commit_group;" ::: "memory")
#define CP_WAIT0()  asm volatile("cp.async.wait_group 0;" ::: "memory")

__device__ __forceinline__ void ldsm_x4(uint32_t& r0, uint32_t& r1, uint32_t& r2, uint32_t& r3,
                                        uint32_t addr) {
    asm volatile("ldmatrix.sync.aligned.m8n8.x4.shared.b16 {%0,%1,%2,%3}, [%4];"
                 : "=r"(r0), "=r"(r1), "=r"(r2), "=r"(r3) : "r"(addr));
}
__device__ __forceinline__ void ldsm_x2(uint32_t& r0, uint32_t& r1, uint32_t addr) {
    asm volatile("ldmatrix.sync.aligned.m8n8.x2.shared.b16 {%0,%1}, [%2];"
                 : "=r"(r0), "=r"(r1) : "r"(addr));
}
__device__ __forceinline__ void mma_16816(float* d, const uint32_t* a, uint32_t b0, uint32_t b1) {
    asm volatile("mma.sync.aligned.m16n8k16.row.col.f32.f16.f16.f32 "
                 "{%0,%1,%2,%3}, {%4,%5,%6,%7}, {%8,%9}, {%0,%1,%2,%3};"
                 : "+f"(d[0]), "+f"(d[1]), "+f"(d[2]), "+f"(d[3])
                 : "r"(a[0]), "r"(a[1]), "r"(a[2]), "r"(a[3]), "r"(b0), "r"(b1));
}

// ---------------------------------------------------------------------------
// Repack: weights -> fp16, [head][stage][n80][k72]; biases.
// ---------------------------------------------------------------------------
__global__ void repack_kernel(const float* __restrict__ wr1, const float* __restrict__ br1,
                              const float* __restrict__ wc1, const float* __restrict__ bc1,
                              const float* __restrict__ wr2, const float* __restrict__ br2,
                              const float* __restrict__ wc2, const float* __restrict__ bc2)
{
    int idx = blockIdx.x * blockDim.x + threadIdx.x;
    if (idx < BPACK_ELEMS) {
        int k     = idx % LDK;
        int n     = (idx / LDK) % 80;
        int stage = (idx / (LDK * 80)) % 36;
        int head  = idx / (LDK * 80 * 36);
        int kc  = stage & 3;
        int tap = stage >> 2;
        float w = 0.0f;
        if (k < 64) {
            int ci = kc * 64 + k;
            const float* wr = head ? wr2 : wr1;
            const float* wc = head ? wc2 : wc1;
            if (n < 24)      w = wr[(n * C_IN + ci) * 9 + tap];
            else if (n < 78) w = wc[((n - 24) * C_IN + ci) * 9 + tap];
        }
        g_bpack[idx] = __float2half_rn(w);
    }
    if (idx < 160) {
        int head = idx / 80, o = idx % 80;
        const float* br = head ? br2 : br1;
        const float* bc = head ? bc2 : bc1;
        float v = 0.0f;
        if (o < 24)      v = br[o];
        else if (o < 78) v = bc[o - 24];
        g_bias[idx] = v;
    }
}

// ---------------------------------------------------------------------------
__device__ __forceinline__ void store_one(float* __restrict__ out, int o, float val,
                                          int n_img, int off_l, int HW, int p, int head)
{
    float bias = g_bias[head * 80 + o];
    int idx;
    if (o < 24) {
        int c = o / 6, a = o % 6;
        idx = n_img * REG_STRIDE_N + c * APW_TOTAL + off_l + a * HW + p;
    } else {
        int oc = o - 24;
        int c = oc / 6, a = oc % 6;
        idx = CONF_BASE + n_img * CLS_STRIDE_N + c * APW_TOTAL + off_l + a * HW + p;
    }
    out[idx] = val + bias;
}

// ---------------------------------------------------------------------------
// Main kernel: 683 CTAs x 256 threads.
// CTAs per level (128 rows over flattened img*HW): {512,128,32,8,2,1}.
// ---------------------------------------------------------------------------
__global__ __launch_bounds__(NTH, 2) void head_kernel(
    const float* __restrict__ f0, const float* __restrict__ f1,
    const float* __restrict__ f2, const float* __restrict__ f3,
    const float* __restrict__ f4, const float* __restrict__ f5,
    float* __restrict__ out)
{
    extern __shared__ char smem_c[];
    const uint32_t sm = smem_u32(smem_c);
    const int t = threadIdx.x;
    const int wid = t >> 5;
    const int lane = t & 31;

    // ---- block -> (level, rem) over flattened img*HW rows ----
    int b = blockIdx.x;
    int level, rem;
    if      (b < 512) { level = 0; rem = b;       }
    else if (b < 640) { level = 1; rem = b - 512; }
    else if (b < 672) { level = 2; rem = b - 640; }
    else if (b < 680) { level = 3; rem = b - 672; }
    else if (b < 682) { level = 4; rem = b - 680; }
    else              { level = 5; rem = b - 682; }
    const int logW = 6 - level;
    const int W  = 1 << logW;
    const int HW = 1 << (2 * logW);
    const int head = (level < 2) ? 0 : 1;
    const float* X = (level == 0) ? f0 : (level == 1) ? f1 : (level == 2) ? f2
                   : (level == 3) ? f3 : (level == 4) ? f4 : f5;
    const int lvl_off[6] = {0, 24576, 30720, 32256, 32640, 32736};
    const int off_l = lvl_off[level];
    const int u0 = rem << 7;

    // ---- A-build mapping: thread -> (row m, half of the 64-ch chunk) ----
    const int m  = t & 127;
    const int kh = t >> 7;
    const int u  = u0 + m;
    const bool rv = (u < (HW << 4));
    const int img = rv ? (u >> (2 * logW)) : 0;
    const int pos = u & (HW - 1);
    const int h0 = pos >> logW;
    const int w0 = pos & (W - 1);
    const float* Xn = X + (long)img * C_IN * HW;

    // ---- MMA mapping: warp grid 4(M) x 2(N), warp tile m32 x n40 ----
    const int wm = (wid & 3) << 5;
    const int wn = (wid >> 2) * 40;
    const int arow = lane & 15, acol = lane >> 4;
    const int brow4 = (lane & 7) + ((lane >> 4) << 3), bcol4 = (lane >> 3) & 1;
    const int brow2 = (lane & 7), bcol2 = (lane >> 3) & 1;

    float acc[2][5][4];
#pragma unroll
    for (int i = 0; i < 2; i++)
#pragma unroll
        for (int j = 0; j < 5; j++)
#pragma unroll
            for (int r = 0; r < 4; r++) acc[i][j][r] = 0.0f;

    const char* bpack_base = (const char*)(g_bpack) +
        (size_t)(head * 36) * BPACK_TILE * sizeof(__half);

    float xs[16];

    // ---- prologue: B(0) cp.async; A(0) LDG+convert+STS into buf0; sync ----
    {
        uint32_t dst = sm + B_OFF;
#pragma unroll
        for (int i = 0; i < 3; i++) {
            int idx = t + i * NTH;
            if (idx < 720) cp_async16(dst + idx * 16, bpack_base + idx * 16);
        }
        CP_COMMIT();

        const int hh = h0 - 1, ww = w0 - 1;   // tap 0: dy=-1, dx=-1; kc 0
        const bool v = rv & ((unsigned)hh < (unsigned)W) & ((unsigned)ww < (unsigned)W);
        const float* aptr = Xn + (v ? (hh * W + ww) : 0) + (kh * 32) * (long)HW;
        char* arow_p = smem_c + m * (LDK * 2) + kh * 64;
#pragma unroll
        for (int g = 0; g < 2; g++) {
#pragma unroll
            for (int j = 0; j < 16; j++) xs[j] = v ? __ldg(aptr + (g * 16 + j) * HW) : 0.0f;
            uint32_t hw_[8];
#pragma unroll
            for (int j = 0; j < 8; j++) {
                __half2 h2 = __floats2half2_rn(xs[2 * j], xs[2 * j + 1]);
                hw_[j] = *reinterpret_cast<uint32_t*>(&h2);
            }
            *reinterpret_cast<uint4*>(arow_p + g * 32)      = make_uint4(hw_[0], hw_[1], hw_[2], hw_[3]);
            *reinterpret_cast<uint4*>(arow_p + g * 32 + 16) = make_uint4(hw_[4], hw_[5], hw_[6], hw_[7]);
        }

        CP_WAIT0();
        __syncthreads();
    }

    for (int s = 0; s < 36; ++s) {
        const bool more = (s + 1 < 36);

        // ---- issue B(s+1) into buf[(s+1)&1] (freed by last stage's sync) ----
        if (more) {
            const char* src = bpack_base + (size_t)(s + 1) * BPACK_TILE * sizeof(__half);
            uint32_t dst = sm + B_OFF + (((s + 1) & 1) ? B_STAGE_B : 0);
#pragma unroll
            for (int i = 0; i < 3; i++) {
                int idx = t + i * NTH;
                if (idx < 720) cp_async16(dst + idx * 16, src + idx * 16);
            }
            CP_COMMIT();
        }

        // ---- A(s+1) gmem address + destination (other A buffer) ----
        bool vN = false;
        const float* aptrN = Xn;
        char* adstN = smem_c + (((s + 1) & 1) ? A_ONE : 0) + m * (LDK * 2) + kh * 64;
        if (more) {
            const int sn = s + 1;
            const int tap = sn >> 2;
            const int dy = tap / 3 - 1, dx = tap % 3 - 1;
            const int hh = h0 + dy, ww = w0 + dx;
            vN = rv & ((unsigned)hh < (unsigned)W) & ((unsigned)ww < (unsigned)W);
            aptrN = Xn + (vN ? (hh * W + ww) : 0) + ((sn & 3) * 64 + kh * 32) * (long)HW;
        }

        // ---- MMA(s) over 4 k16 steps; A(s+1) streamed through the loop ----
        const uint32_t abuf = sm + ((s & 1) ? A_ONE : 0);
        const uint32_t bbuf = sm + B_OFF + ((s & 1) ? B_STAGE_B : 0);
#pragma unroll
        for (int ks = 0; ks < 4; ks++) {
            const int kb = ks * 32;

            // streamed A(s+1) build: LDG at ks0/ks2, convert+STS at ks1/ks3
            if (more) {
                if (ks == 0 || ks == 2) {
                    const int g = ks >> 1;
#pragma unroll
                    for (int j = 0; j < 16; j++)
                        xs[j] = vN ? __ldg(aptrN + (g * 16 + j) * HW) : 0.0f;
                } else {
                    const int g = ks >> 1;
                    uint32_t hw_[8];
#pragma unroll
                    for (int j = 0; j < 8; j++) {
                        __half2 h2 = __floats2half2_rn(xs[2 * j], xs[2 * j + 1]);
                        hw_[j] = *reinterpret_cast<uint32_t*>(&h2);
                    }
                    *reinterpret_cast<uint4*>(adstN + g * 32)      = make_uint4(hw_[0], hw_[1], hw_[2], hw_[3]);
                    *reinterpret_cast<uint4*>(adstN + g * 32 + 16) = make_uint4(hw_[4], hw_[5], hw_[6], hw_[7]);
                }
            }

            uint32_t ah[2][4];
#pragma unroll
            for (int mi = 0; mi < 2; mi++) {
                uint32_t ad = abuf + (wm + mi * 16 + arow) * (LDK * 2) + kb + acol * 16;
                ldsm_x4(ah[mi][0], ah[mi][1], ah[mi][2], ah[mi][3], ad);
            }

            uint32_t bh[10];
            {
                uint32_t b0 = bbuf + kb;
                ldsm_x4(bh[0], bh[1], bh[2], bh[3], b0 + (wn + brow4) * (LDK * 2) + bcol4 * 16);
                ldsm_x4(bh[4], bh[5], bh[6], bh[7], b0 + (wn + 16 + brow4) * (LDK * 2) + bcol4 * 16);
                ldsm_x2(bh[8], bh[9],             b0 + (wn + 32 + brow2) * (LDK * 2) + bcol2 * 16);
            }
#pragma unroll
            for (int mi = 0; mi < 2; mi++)
#pragma unroll
                for (int nj = 0; nj < 5; nj++)
                    mma_16816(acc[mi][nj], ah[mi], bh[2 * nj], bh[2 * nj + 1]);
        }

        CP_WAIT0();        // B(s+1) landed (issued a full stage ago)
        __syncthreads();   // handoff: A(s+1) writes + B buffers visible
    }

    // ---- epilogue: bias + scatter ----
#pragma unroll
    for (int mi = 0; mi < 2; mi++) {
        const int ur0 = u0 + wm + mi * 16 + (lane >> 2);
#pragma unroll
        for (int half = 0; half < 2; half++) {
            const int ur = ur0 + half * 8;
            if (ur >= (HW << 4)) continue;
            const int img_e = ur >> (2 * logW);
            const int p_e   = ur & (HW - 1);
#pragma unroll
            for (int nj = 0; nj < 5; nj++) {
                const int o0 = wn + nj * 8 + (lane & 3) * 2;
                const float v0 = acc[mi][nj][half * 2];
                const float v1 = acc[mi][nj][half * 2 + 1];
                if (o0 < 78)     store_one(out, o0,     v0, img_e, off_l, HW, p_e, head);
                if (o0 + 1 < 78) store_one(out, o0 + 1, v1, img_e, off_l, HW, p_e, head);
            }
        }
    }
}

// ---------------------------------------------------------------------------
extern "C" void kernel_launch(void* const* d_in, const int* in_sizes, int n_in,
                              void* d_out, int out_size)
{
    cudaFuncSetAttribute(head_kernel, cudaFuncAttributeMaxDynamicSharedMemorySize, SMEM_TOTAL);

    repack_kernel<<<(BPACK_ELEMS + NTH - 1) / NTH, NTH>>>(
        (const float*)d_in[6],  (const float*)d_in[7],
        (const float*)d_in[8],  (const float*)d_in[9],
        (const float*)d_in[10], (const float*)d_in[11],
        (const float*)d_in[12], (const float*)d_in[13]);

    head_kernel<<<683, NTH, SMEM_TOTAL>>>(
        (const float*)d_in[0], (const float*)d_in[1], (const float*)d_in[2],
        (const float*)d_in[3], (const float*)d_in[4], (const float*)d_in[5],
        (float*)d_out);
}

// round 11
// speedup vs baseline: 1.0123x; 1.0123x over previous
#include <cuda_runtime.h>
#include <cuda_fp16.h>
#include <cstdint>

// ============================================================================
// RetinaNet heads: pure fp16 implicit GEMM via mma.sync (HMMA) on sm_103.
// Round 11: 18 stages of K=128 (halves barrier count), double-buffered A,
// A LDGs issued with 3-4 k-steps of slack before their converts, one
// __syncthreads per stage. B cp.async double-buffer a stage ahead.
// ============================================================================

#define NTH 256
#define C_IN 256
#define APW_TOTAL 32760
#define REG_STRIDE_N (4 * APW_TOTAL)
#define CLS_STRIDE_N (9 * APW_TOTAL)
#define CONF_BASE (16 * 4 * APW_TOTAL)

#define LDK 136                       // smem row stride in halves (272 B)
#define ROWB (LDK * 2)                // 272
#define A_ONE (128 * ROWB)            // 34816 B per A buffer
#define A_BYTES (2 * A_ONE)           // 69632
#define B_STAGE_B (80 * ROWB)         // 21760 B per B stage
#define B_OFF A_BYTES
#define SMEM_TOTAL (A_BYTES + 2 * B_STAGE_B)   // 113152

// B pack: [head 2][stage 18][n 80][k 136] halves (stage = tap*2 + chunk)
#define BPACK_TILE (80 * LDK)         // 10880
#define BPACK_ELEMS (2 * 18 * BPACK_TILE)
__device__ __align__(16) __half g_bpack[BPACK_ELEMS];
__device__ float g_bias[2 * 80];

// ---------------------------------------------------------------------------
__device__ __forceinline__ uint32_t smem_u32(const void* p) {
    uint32_t a;
    asm("{ .reg .u64 t; cvta.to.shared.u64 t, %1; cvt.u32.u64 %0, t; }" : "=r"(a) : "l"(p));
    return a;
}
__device__ __forceinline__ void cp_async16(uint32_t dst, const void* src) {
    asm volatile("cp.async.cg.shared.global [%0], [%1], 16;" :: "r"(dst), "l"(src));
}
#define CP_COMMIT() asm volatile("cp.async.commit_group;" ::: "memory")
#define CP_WAIT0()  asm volatile("cp.async.wait_group 0;" ::: "memory")

__device__ __forceinline__ void ldsm_x4(uint32_t& r0, uint32_t& r1, uint32_t& r2, uint32_t& r3,
                                        uint32_t addr) {
    asm volatile("ldmatrix.sync.aligned.m8n8.x4.shared.b16 {%0,%1,%2,%3}, [%4];"
                 : "=r"(r0), "=r"(r1), "=r"(r2), "=r"(r3) : "r"(addr));
}
__device__ __forceinline__ void ldsm_x2(uint32_t& r0, uint32_t& r1, uint32_t addr) {
    asm volatile("ldmatrix.sync.aligned.m8n8.x2.shared.b16 {%0,%1}, [%2];"
                 : "=r"(r0), "=r"(r1) : "r"(addr));
}
__device__ __forceinline__ void mma_16816(float* d, const uint32_t* a, uint32_t b0, uint32_t b1) {
    asm volatile("mma.sync.aligned.m16n8k16.row.col.f32.f16.f16.f32 "
                 "{%0,%1,%2,%3}, {%4,%5,%6,%7}, {%8,%9}, {%0,%1,%2,%3};"
                 : "+f"(d[0]), "+f"(d[1]), "+f"(d[2]), "+f"(d[3])
                 : "r"(a[0]), "r"(a[1]), "r"(a[2]), "r"(a[3]), "r"(b0), "r"(b1));
}

// ---------------------------------------------------------------------------
// Repack: weights -> fp16, [head][stage][n80][k136]; biases.
// ---------------------------------------------------------------------------
__global__ void repack_kernel(const float* __restrict__ wr1, const float* __restrict__ br1,
                              const float* __restrict__ wc1, const float* __restrict__ bc1,
                              const float* __restrict__ wr2, const float* __restrict__ br2,
                              const float* __restrict__ wc2, const float* __restrict__ bc2)
{
    int idx = blockIdx.x * blockDim.x + threadIdx.x;
    if (idx < BPACK_ELEMS) {
        int k     = idx % LDK;
        int n     = (idx / LDK) % 80;
        int stage = (idx / (LDK * 80)) % 18;
        int head  = idx / (LDK * 80 * 18);
        int chunk = stage & 1;
        int tap   = stage >> 1;
        float w = 0.0f;
        if (k < 128) {
            int ci = chunk * 128 + k;
            const float* wr = head ? wr2 : wr1;
            const float* wc = head ? wc2 : wc1;
            if (n < 24)      w = wr[(n * C_IN + ci) * 9 + tap];
            else if (n < 78) w = wc[((n - 24) * C_IN + ci) * 9 + tap];
        }
        g_bpack[idx] = __float2half_rn(w);
    }
    if (idx < 160) {
        int head = idx / 80, o = idx % 80;
        const float* br = head ? br2 : br1;
        const float* bc = head ? bc2 : bc1;
        float v = 0.0f;
        if (o < 24)      v = br[o];
        else if (o < 78) v = bc[o - 24];
        g_bias[idx] = v;
    }
}

// ---------------------------------------------------------------------------
__device__ __forceinline__ void store_one(float* __restrict__ out, int o, float val,
                                          int n_img, int off_l, int HW, int p, int head)
{
    float bias = g_bias[head * 80 + o];
    int idx;
    if (o < 24) {
        int c = o / 6, a = o % 6;
        idx = n_img * REG_STRIDE_N + c * APW_TOTAL + off_l + a * HW + p;
    } else {
        int oc = o - 24;
        int c = oc / 6, a = oc % 6;
        idx = CONF_BASE + n_img * CLS_STRIDE_N + c * APW_TOTAL + off_l + a * HW + p;
    }
    out[idx] = val + bias;
}

// ---------------------------------------------------------------------------
// Main kernel: 683 CTAs x 256 threads.
// CTAs per level (128 rows over flattened img*HW): {512,128,32,8,2,1}.
// ---------------------------------------------------------------------------
__global__ __launch_bounds__(NTH, 2) void head_kernel(
    const float* __restrict__ f0, const float* __restrict__ f1,
    const float* __restrict__ f2, const float* __restrict__ f3,
    const float* __restrict__ f4, const float* __restrict__ f5,
    float* __restrict__ out)
{
    extern __shared__ char smem_c[];
    const uint32_t sm = smem_u32(smem_c);
    const int t = threadIdx.x;
    const int wid = t >> 5;
    const int lane = t & 31;

    // ---- block -> (level, rem) over flattened img*HW rows ----
    int b = blockIdx.x;
    int level, rem;
    if      (b < 512) { level = 0; rem = b;       }
    else if (b < 640) { level = 1; rem = b - 512; }
    else if (b < 672) { level = 2; rem = b - 640; }
    else if (b < 680) { level = 3; rem = b - 672; }
    else if (b < 682) { level = 4; rem = b - 680; }
    else              { level = 5; rem = b - 682; }
    const int logW = 6 - level;
    const int W  = 1 << logW;
    const int HW = 1 << (2 * logW);
    const int head = (level < 2) ? 0 : 1;
    const float* X = (level == 0) ? f0 : (level == 1) ? f1 : (level == 2) ? f2
                   : (level == 3) ? f3 : (level == 4) ? f4 : f5;
    const int lvl_off[6] = {0, 24576, 30720, 32256, 32640, 32736};
    const int off_l = lvl_off[level];
    const int u0 = rem << 7;

    // ---- A-build mapping: thread -> (row m, 64-ch half of the 128 chunk) ----
    const int m  = t & 127;
    const int kh = t >> 7;                 // channels kh*64 .. kh*64+63
    const int u  = u0 + m;
    const bool rv = (u < (HW << 4));
    const int img = rv ? (u >> (2 * logW)) : 0;
    const int pos = u & (HW - 1);
    const int h0 = pos >> logW;
    const int w0 = pos & (W - 1);
    const float* Xn = X + (long)img * C_IN * HW;

    // ---- MMA mapping: warp grid 4(M) x 2(N), warp tile m32 x n40 ----
    const int wm = (wid & 3) << 5;
    const int wn = (wid >> 2) * 40;
    const int arow = lane & 15, acol = lane >> 4;
    const int brow4 = (lane & 7) + ((lane >> 4) << 3), bcol4 = (lane >> 3) & 1;
    const int brow2 = (lane & 7), bcol2 = (lane >> 3) & 1;

    float acc[2][5][4];
#pragma unroll
    for (int i = 0; i < 2; i++)
#pragma unroll
        for (int j = 0; j < 5; j++)
#pragma unroll
            for (int r = 0; r < 4; r++) acc[i][j][r] = 0.0f;

    const char* bpack_base = (const char*)(g_bpack) +
        (size_t)(head * 18) * BPACK_TILE * sizeof(__half);

    float xs[32];

    // ---- prologue: B(0) cp.async; A(0) (both 32-batches) into buf0; sync ----
    {
        uint32_t dst = sm + B_OFF;
#pragma unroll
        for (int i = 0; i < 6; i++) {
            int idx = t + i * NTH;
            if (idx < 1360) cp_async16(dst + idx * 16, bpack_base + idx * 16);
        }
        CP_COMMIT();

        const int hh = h0 - 1, ww = w0 - 1;   // tap 0: dy=-1, dx=-1; chunk 0
        const bool v = rv & ((unsigned)hh < (unsigned)W) & ((unsigned)ww < (unsigned)W);
        const float* aptr = Xn + (v ? (hh * W + ww) : 0) + (kh * 64) * (long)HW;
        char* arow_p = smem_c + m * ROWB + kh * 128;
#pragma unroll
        for (int bt = 0; bt < 2; bt++) {
#pragma unroll
            for (int j = 0; j < 32; j++) xs[j] = v ? __ldg(aptr + (bt * 32 + j) * HW) : 0.0f;
            uint32_t hw_[16];
#pragma unroll
            for (int j = 0; j < 16; j++) {
                __half2 h2 = __floats2half2_rn(xs[2 * j], xs[2 * j + 1]);
                hw_[j] = *reinterpret_cast<uint32_t*>(&h2);
            }
            *reinterpret_cast<uint4*>(arow_p + bt * 64)      = make_uint4(hw_[0], hw_[1], hw_[2], hw_[3]);
            *reinterpret_cast<uint4*>(arow_p + bt * 64 + 16) = make_uint4(hw_[4], hw_[5], hw_[6], hw_[7]);
            *reinterpret_cast<uint4*>(arow_p + bt * 64 + 32) = make_uint4(hw_[8], hw_[9], hw_[10], hw_[11]);
            *reinterpret_cast<uint4*>(arow_p + bt * 64 + 48) = make_uint4(hw_[12], hw_[13], hw_[14], hw_[15]);
        }

        CP_WAIT0();
        __syncthreads();
    }

    for (int s = 0; s < 18; ++s) {
        const bool more = (s + 1 < 18);

        // ---- issue B(s+1) into buf[(s+1)&1] (freed by last stage's sync) ----
        if (more) {
            const char* src = bpack_base + (size_t)(s + 1) * BPACK_TILE * sizeof(__half);
            uint32_t dst = sm + B_OFF + (((s + 1) & 1) ? B_STAGE_B : 0);
#pragma unroll
            for (int i = 0; i < 6; i++) {
                int idx = t + i * NTH;
                if (idx < 1360) cp_async16(dst + idx * 16, src + idx * 16);
            }
            CP_COMMIT();
        }

        // ---- A(s+1) gmem address + destination (other A buffer) ----
        bool vN = false;
        const float* aptrN = Xn;
        char* adstN = smem_c + (((s + 1) & 1) ? A_ONE : 0) + m * ROWB + kh * 128;
        if (more) {
            const int sn = s + 1;
            const int tap = sn >> 1;
            const int dy = tap / 3 - 1, dx = tap % 3 - 1;
            const int hh = h0 + dy, ww = w0 + dx;
            vN = rv & ((unsigned)hh < (unsigned)W) & ((unsigned)ww < (unsigned)W);
            aptrN = Xn + (vN ? (hh * W + ww) : 0) + ((sn & 1) * 128 + kh * 64) * (long)HW;
        }

        // ---- A(s+1) batch0 LDG at stage top (3 k-steps of slack) ----
        if (more) {
#pragma unroll
            for (int j = 0; j < 32; j++) xs[j] = vN ? __ldg(aptrN + j * HW) : 0.0f;
        }

        // ---- MMA(s): 8 k16 steps; batch0 cvt+STS & batch1 LDG at ks==3 ----
        const uint32_t abuf = sm + ((s & 1) ? A_ONE : 0);
        const uint32_t bbuf = sm + B_OFF + ((s & 1) ? B_STAGE_B : 0);
#pragma unroll
        for (int ks = 0; ks < 8; ks++) {
            const int kb = ks * 32;

            if (ks == 3 && more) {
                uint32_t hw_[16];
#pragma unroll
                for (int j = 0; j < 16; j++) {
                    __half2 h2 = __floats2half2_rn(xs[2 * j], xs[2 * j + 1]);
                    hw_[j] = *reinterpret_cast<uint32_t*>(&h2);
                }
                *reinterpret_cast<uint4*>(adstN)      = make_uint4(hw_[0], hw_[1], hw_[2], hw_[3]);
                *reinterpret_cast<uint4*>(adstN + 16) = make_uint4(hw_[4], hw_[5], hw_[6], hw_[7]);
                *reinterpret_cast<uint4*>(adstN + 32) = make_uint4(hw_[8], hw_[9], hw_[10], hw_[11]);
                *reinterpret_cast<uint4*>(adstN + 48) = make_uint4(hw_[12], hw_[13], hw_[14], hw_[15]);
                // batch1 LDG (4 k-steps of slack to the post-loop convert)
#pragma unroll
                for (int j = 0; j < 32; j++) xs[j] = vN ? __ldg(aptrN + (32 + j) * HW) : 0.0f;
            }

            uint32_t ah[2][4];
#pragma unroll
            for (int mi = 0; mi < 2; mi++) {
                uint32_t ad = abuf + (wm + mi * 16 + arow) * ROWB + kb + acol * 16;
                ldsm_x4(ah[mi][0], ah[mi][1], ah[mi][2], ah[mi][3], ad);
            }

            uint32_t bh[10];
            {
                uint32_t b0 = bbuf + kb;
                ldsm_x4(bh[0], bh[1], bh[2], bh[3], b0 + (wn + brow4) * ROWB + bcol4 * 16);
                ldsm_x4(bh[4], bh[5], bh[6], bh[7], b0 + (wn + 16 + brow4) * ROWB + bcol4 * 16);
                ldsm_x2(bh[8], bh[9],             b0 + (wn + 32 + brow2) * ROWB + bcol2 * 16);
            }
#pragma unroll
            for (int mi = 0; mi < 2; mi++)
#pragma unroll
                for (int nj = 0; nj < 5; nj++)
                    mma_16816(acc[mi][nj], ah[mi], bh[2 * nj], bh[2 * nj + 1]);
        }

        // ---- A(s+1) batch1 convert + STS ----
        if (more) {
            uint32_t hw_[16];
#pragma unroll
            for (int j = 0; j < 16; j++) {
                __half2 h2 = __floats2half2_rn(xs[2 * j], xs[2 * j + 1]);
                hw_[j] = *reinterpret_cast<uint32_t*>(&h2);
            }
            *reinterpret_cast<uint4*>(adstN + 64)  = make_uint4(hw_[0], hw_[1], hw_[2], hw_[3]);
            *reinterpret_cast<uint4*>(adstN + 80)  = make_uint4(hw_[4], hw_[5], hw_[6], hw_[7]);
            *reinterpret_cast<uint4*>(adstN + 96)  = make_uint4(hw_[8], hw_[9], hw_[10], hw_[11]);
            *reinterpret_cast<uint4*>(adstN + 112) = make_uint4(hw_[12], hw_[13], hw_[14], hw_[15]);
        }

        CP_WAIT0();        // B(s+1) landed (issued a full stage ago)
        __syncthreads();   // handoff: A(s+1) writes + B buffers visible
    }

    // ---- epilogue: bias + scatter ----
#pragma unroll
    for (int mi = 0; mi < 2; mi++) {
        const int ur0 = u0 + wm + mi * 16 + (lane >> 2);
#pragma unroll
        for (int half = 0; half < 2; half++) {
            const int ur = ur0 + half * 8;
            if (ur >= (HW << 4)) continue;
            const int img_e = ur >> (2 * logW);
            const int p_e   = ur & (HW - 1);
#pragma unroll
            for (int nj = 0; nj < 5; nj++) {
                const int o0 = wn + nj * 8 + (lane & 3) * 2;
                const float v0 = acc[mi][nj][half * 2];
                const float v1 = acc[mi][nj][half * 2 + 1];
                if (o0 < 78)     store_one(out, o0,     v0, img_e, off_l, HW, p_e, head);
                if (o0 + 1 < 78) store_one(out, o0 + 1, v1, img_e, off_l, HW, p_e, head);
            }
        }
    }
}

// ---------------------------------------------------------------------------
extern "C" void kernel_launch(void* const* d_in, const int* in_sizes, int n_in,
                              void* d_out, int out_size)
{
    cudaFuncSetAttribute(head_kernel, cudaFuncAttributeMaxDynamicSharedMemorySize, SMEM_TOTAL);

    repack_kernel<<<(BPACK_ELEMS + NTH - 1) / NTH, NTH>>>(
        (const float*)d_in[6],  (const float*)d_in[7],
        (const float*)d_in[8],  (const float*)d_in[9],
        (const float*)d_in[10], (const float*)d_in[11],
        (const float*)d_in[12], (const float*)d_in[13]);

    head_kernel<<<683, NTH, SMEM_TOTAL>>>(
        (const float*)d_in[0], (const float*)d_in[1], (const float*)d_in[2],
        (const float*)d_in[3], (const float*)d_in[4], (const float*)d_in[5],
        (float*)d_out);
}

// round 12
// speedup vs baseline: 1.2330x; 1.2179x over previous
#include <cuda_runtime.h>
#include <cuda_fp16.h>
#include <cstdint>

// ============================================================================
// RetinaNet heads: pure fp16 implicit GEMM via mma.sync (HMMA) on sm_103.
// Round 12: pre-pass transposes activations to fp16 NHWC ([img*pos][256ch],
// channels contiguous), so the main kernel loads BOTH operand tiles via
// cp.async. Main loop = cp.async issue + ldsm + mma only (no LDG / convert /
// STS on the critical path). Boundary taps zero-filled with st.shared.
// 18 stages of K=128, double-buffered A and B, one __syncthreads per stage.
// ============================================================================

#define NTH 256
#define C_IN 256
#define APW_TOTAL 32760
#define REG_STRIDE_N (4 * APW_TOTAL)
#define CLS_STRIDE_N (9 * APW_TOTAL)
#define CONF_BASE (16 * 4 * APW_TOTAL)

#define LDK 136                       // smem row stride in halves (272 B)
#define ROWB (LDK * 2)                // 272
#define A_ONE (128 * ROWB)            // 34816 B per A buffer
#define A_BYTES (2 * A_ONE)
#define B_STAGE_B (80 * ROWB)         // 21760 B per B stage
#define B_OFF A_BYTES
#define SMEM_TOTAL (A_BYTES + 2 * B_STAGE_B)   // 113152

// fp16 NHWC activations: [level-flattened img*pos][256 ch]
// positions per level (16 imgs): 65536,16384,4096,1024,256,64 ; total 87360
#define TOT_POS 87360
__device__ __align__(16) __half g_afp16[(size_t)TOT_POS * 256];

// B pack: [head 2][stage 18][n 80][k 136] halves (stage = tap*2 + chunk)
#define BPACK_TILE (80 * LDK)
#define BPACK_ELEMS (2 * 18 * BPACK_TILE)
__device__ __align__(16) __half g_bpack[BPACK_ELEMS];
__device__ float g_bias[2 * 80];

// ---------------------------------------------------------------------------
__device__ __forceinline__ uint32_t smem_u32(const void* p) {
    uint32_t a;
    asm("{ .reg .u64 t; cvta.to.shared.u64 t, %1; cvt.u32.u64 %0, t; }" : "=r"(a) : "l"(p));
    return a;
}
__device__ __forceinline__ void cp_async16(uint32_t dst, const void* src) {
    asm volatile("cp.async.cg.shared.global [%0], [%1], 16;" :: "r"(dst), "l"(src));
}
#define CP_COMMIT() asm volatile("cp.async.commit_group;" ::: "memory")
#define CP_WAIT0()  asm volatile("cp.async.wait_group 0;" ::: "memory")

__device__ __forceinline__ void ldsm_x4(uint32_t& r0, uint32_t& r1, uint32_t& r2, uint32_t& r3,
                                        uint32_t addr) {
    asm volatile("ldmatrix.sync.aligned.m8n8.x4.shared.b16 {%0,%1,%2,%3}, [%4];"
                 : "=r"(r0), "=r"(r1), "=r"(r2), "=r"(r3) : "r"(addr));
}
__device__ __forceinline__ void ldsm_x2(uint32_t& r0, uint32_t& r1, uint32_t addr) {
    asm volatile("ldmatrix.sync.aligned.m8n8.x2.shared.b16 {%0,%1}, [%2];"
                 : "=r"(r0), "=r"(r1) : "r"(addr));
}
__device__ __forceinline__ void mma_16816(float* d, const uint32_t* a, uint32_t b0, uint32_t b1) {
    asm volatile("mma.sync.aligned.m16n8k16.row.col.f32.f16.f16.f32 "
                 "{%0,%1,%2,%3}, {%4,%5,%6,%7}, {%8,%9}, {%0,%1,%2,%3};"
                 : "+f"(d[0]), "+f"(d[1]), "+f"(d[2]), "+f"(d[3])
                 : "r"(a[0]), "r"(a[1]), "r"(a[2]), "r"(a[3]), "r"(b0), "r"(b1));
}

// ---------------------------------------------------------------------------
// Transpose pre-pass: f32 NCHW -> fp16 [img*pos][256ch].
// 1365 blocks x 256 threads; each block = 64 flattened positions of a level.
// ---------------------------------------------------------------------------
#define LDT 264   // smem tile row stride in halves
__global__ __launch_bounds__(NTH) void transpose_kernel(
    const float* __restrict__ f0, const float* __restrict__ f1,
    const float* __restrict__ f2, const float* __restrict__ f3,
    const float* __restrict__ f4, const float* __restrict__ f5)
{
    __shared__ __half tile[64 * LDT];
    int b = blockIdx.x;
    int level, tl;
    if      (b < 1024) { level = 0; tl = b;        }
    else if (b < 1280) { level = 1; tl = b - 1024; }
    else if (b < 1344) { level = 2; tl = b - 1280; }
    else if (b < 1360) { level = 3; tl = b - 1344; }
    else if (b < 1364) { level = 4; tl = b - 1360; }
    else               { level = 5; tl = b - 1364; }
    const int logW = 6 - level;
    const int HW = 1 << (2 * logW);
    const float* X = (level == 0) ? f0 : (level == 1) ? f1 : (level == 2) ? f2
                   : (level == 3) ? f3 : (level == 4) ? f4 : f5;
    const int lvl_pos_base[6] = {0, 65536, 81920, 86016, 87040, 87296};
    const int fp = tl << 6;              // first flattened pos of this tile

    const int t = threadIdx.x;
    const int px = t & 63;
    const int cg = t >> 6;               // channel group (64 ch each)

    {
        const int gp  = fp + px;
        const int img = gp >> (2 * logW);
        const int pos = gp & (HW - 1);
        const float* src = X + (size_t)img * C_IN * HW + pos;
#pragma unroll
        for (int j = 0; j < 32; j++) {
            const int ch = cg * 64 + 2 * j;
            float a  = src[(size_t)ch * HW];
            float bb = src[(size_t)(ch + 1) * HW];
            __half2 h2 = __floats2half2_rn(a, bb);
            *reinterpret_cast<__half2*>(&tile[px * LDT + ch]) = h2;
        }
    }
    __syncthreads();

    const size_t out_base = ((size_t)(lvl_pos_base[level] + fp)) << 8;  // halves
#pragma unroll
    for (int i = 0; i < 8; i++) {
        const int c = t + i * NTH;       // 0..2047: 64 pos x 32 16B-chunks
        const int p = c >> 5, col = c & 31;
        uint4 v = *reinterpret_cast<const uint4*>(&tile[p * LDT + col * 8]);
        *reinterpret_cast<uint4*>(&g_afp16[out_base + ((size_t)p << 8) + col * 8]) = v;
    }
}

// ---------------------------------------------------------------------------
// Repack: weights -> fp16, [head][stage][n80][k136]; biases.
// ---------------------------------------------------------------------------
__global__ void repack_kernel(const float* __restrict__ wr1, const float* __restrict__ br1,
                              const float* __restrict__ wc1, const float* __restrict__ bc1,
                              const float* __restrict__ wr2, const float* __restrict__ br2,
                              const float* __restrict__ wc2, const float* __restrict__ bc2)
{
    int idx = blockIdx.x * blockDim.x + threadIdx.x;
    if (idx < BPACK_ELEMS) {
        int k     = idx % LDK;
        int n     = (idx / LDK) % 80;
        int stage = (idx / (LDK * 80)) % 18;
        int head  = idx / (LDK * 80 * 18);
        int chunk = stage & 1;
        int tap   = stage >> 1;
        float w = 0.0f;
        if (k < 128) {
            int ci = chunk * 128 + k;
            const float* wr = head ? wr2 : wr1;
            const float* wc = head ? wc2 : wc1;
            if (n < 24)      w = wr[(n * C_IN + ci) * 9 + tap];
            else if (n < 78) w = wc[((n - 24) * C_IN + ci) * 9 + tap];
        }
        g_bpack[idx] = __float2half_rn(w);
    }
    if (idx < 160) {
        int head = idx / 80, o = idx % 80;
        const float* br = head ? br2 : br1;
        const float* bc = head ? bc2 : bc1;
        float v = 0.0f;
        if (o < 24)      v = br[o];
        else if (o < 78) v = bc[o - 24];
        g_bias[idx] = v;
    }
}

// ---------------------------------------------------------------------------
__device__ __forceinline__ void store_one(float* __restrict__ out, int o, float val,
                                          int n_img, int off_l, int HW, int p, int head)
{
    float bias = g_bias[head * 80 + o];
    int idx;
    if (o < 24) {
        int c = o / 6, a = o % 6;
        idx = n_img * REG_STRIDE_N + c * APW_TOTAL + off_l + a * HW + p;
    } else {
        int oc = o - 24;
        int c = oc / 6, a = oc % 6;
        idx = CONF_BASE + n_img * CLS_STRIDE_N + c * APW_TOTAL + off_l + a * HW + p;
    }
    out[idx] = val + bias;
}

// ---------------------------------------------------------------------------
// Main kernel: 683 CTAs x 256 threads.
// CTAs per level (128 rows over flattened img*HW): {512,128,32,8,2,1}.
// ---------------------------------------------------------------------------
__global__ __launch_bounds__(NTH, 2) void head_kernel(float* __restrict__ out)
{
    extern __shared__ char smem_c[];
    const uint32_t sm = smem_u32(smem_c);
    const int t = threadIdx.x;
    const int wid = t >> 5;
    const int lane = t & 31;

    // ---- block -> (level, rem) over flattened img*HW rows ----
    int b = blockIdx.x;
    int level, rem;
    if      (b < 512) { level = 0; rem = b;       }
    else if (b < 640) { level = 1; rem = b - 512; }
    else if (b < 672) { level = 2; rem = b - 640; }
    else if (b < 680) { level = 3; rem = b - 672; }
    else if (b < 682) { level = 4; rem = b - 680; }
    else              { level = 5; rem = b - 682; }
    const int logW = 6 - level;
    const int W  = 1 << logW;
    const int HW = 1 << (2 * logW);
    const int head = (level < 2) ? 0 : 1;
    const int lvl_off[6] = {0, 24576, 30720, 32256, 32640, 32736};
    const int lvl_pos_base[6] = {0, 65536, 81920, 86016, 87040, 87296};
    const int off_l = lvl_off[level];
    const int lvl_pos = lvl_pos_base[level];
    const int u0 = rem << 7;

    // ---- A cp.async mapping: thread t covers rows r0c+16i (i=0..7), col colA ----
    const int r0c  = t >> 4;             // 0..15
    const int colA = t & 15;             // 16B chunk within 256B row
    int hR[8], wR[8], pbR[8];
#pragma unroll
    for (int i = 0; i < 8; i++) {
        const int row = r0c + (i << 4);
        const int ur = u0 + row;
        const bool ok = ur < (HW << 4);
        const int posr = ur & (HW - 1);
        hR[i] = ok ? (posr >> logW) : -100;     // poisoned -> always invalid
        wR[i] = posr & (W - 1);
        pbR[i] = lvl_pos + (ur - posr);          // level base + img*HW
    }

    // ---- MMA mapping: warp grid 4(M) x 2(N), warp tile m32 x n40 ----
    const int wm = (wid & 3) << 5;
    const int wn = (wid >> 2) * 40;
    const int arow = lane & 15, acol = lane >> 4;
    const int brow4 = (lane & 7) + ((lane >> 4) << 3), bcol4 = (lane >> 3) & 1;
    const int brow2 = (lane & 7), bcol2 = (lane >> 3) & 1;

    float acc[2][5][4];
#pragma unroll
    for (int i = 0; i < 2; i++)
#pragma unroll
        for (int j = 0; j < 5; j++)
#pragma unroll
            for (int r = 0; r < 4; r++) acc[i][j][r] = 0.0f;

    const char* bpack_base = (const char*)(g_bpack) +
        (size_t)(head * 18) * BPACK_TILE * sizeof(__half);

    // ---- prologue: A(0) + B(0) cp.async; commit; wait; sync ----
    {
        // A(0): tap 0 (dy=-1,dx=-1), chunk 0
        const uint32_t adst = sm;
#pragma unroll
        for (int i = 0; i < 8; i++) {
            const int hh = hR[i] - 1, ww = wR[i] - 1;
            const bool v = ((unsigned)hh < (unsigned)W) & ((unsigned)ww < (unsigned)W);
            const uint32_t doff = (uint32_t)(r0c + (i << 4)) * ROWB + colA * 16;
            if (v) {
                const __half* sp = g_afp16 +
                    (((size_t)(pbR[i] + hh * W + ww)) << 8) + (colA << 3);
                cp_async16(adst + doff, sp);
            } else {
                *reinterpret_cast<uint4*>(smem_c + doff) = make_uint4(0, 0, 0, 0);
            }
        }
        // B(0)
        const uint32_t bdst = sm + B_OFF;
#pragma unroll
        for (int i = 0; i < 6; i++) {
            int idx = t + i * NTH;
            if (idx < 1360) cp_async16(bdst + idx * 16, bpack_base + idx * 16);
        }
        CP_COMMIT();
        CP_WAIT0();
        __syncthreads();
    }

    for (int s = 0; s < 18; ++s) {
        const bool more = (s + 1 < 18);

        // ---- issue A(s+1) + B(s+1) into the other buffers ----
        if (more) {
            const int sn = s + 1;
            const int tap = sn >> 1;
            const int dy = tap / 3 - 1, dx = tap % 3 - 1;
            const int chunk = sn & 1;
            const uint32_t abase = sm + (chunk ? A_ONE : 0);
            char* abase_c = smem_c + (chunk ? A_ONE : 0);
#pragma unroll
            for (int i = 0; i < 8; i++) {
                const int hh = hR[i] + dy, ww = wR[i] + dx;
                const bool v = ((unsigned)hh < (unsigned)W) & ((unsigned)ww < (unsigned)W);
                const uint32_t doff = (uint32_t)(r0c + (i << 4)) * ROWB + colA * 16;
                if (v) {
                    const __half* sp = g_afp16 +
                        (((size_t)(pbR[i] + hh * W + ww)) << 8) + (chunk << 7) + (colA << 3);
                    cp_async16(abase + doff, sp);
                } else {
                    *reinterpret_cast<uint4*>(abase_c + doff) = make_uint4(0, 0, 0, 0);
                }
            }
            const char* src = bpack_base + (size_t)sn * BPACK_TILE * sizeof(__half);
            const uint32_t bdst = sm + B_OFF + (chunk ? B_STAGE_B : 0);
#pragma unroll
            for (int i = 0; i < 6; i++) {
                int idx = t + i * NTH;
                if (idx < 1360) cp_async16(bdst + idx * 16, src + idx * 16);
            }
            CP_COMMIT();
        }

        // ---- MMA(s): 8 k16 steps ----
        const uint32_t abuf = sm + ((s & 1) ? A_ONE : 0);
        const uint32_t bbuf = sm + B_OFF + ((s & 1) ? B_STAGE_B : 0);
#pragma unroll
        for (int ks = 0; ks < 8; ks++) {
            const int kb = ks * 32;

            uint32_t ah[2][4];
#pragma unroll
            for (int mi = 0; mi < 2; mi++) {
                uint32_t ad = abuf + (wm + mi * 16 + arow) * ROWB + kb + acol * 16;
                ldsm_x4(ah[mi][0], ah[mi][1], ah[mi][2], ah[mi][3], ad);
            }

            uint32_t bh[10];
            {
                uint32_t b0 = bbuf + kb;
                ldsm_x4(bh[0], bh[1], bh[2], bh[3], b0 + (wn + brow4) * ROWB + bcol4 * 16);
                ldsm_x4(bh[4], bh[5], bh[6], bh[7], b0 + (wn + 16 + brow4) * ROWB + bcol4 * 16);
                ldsm_x2(bh[8], bh[9],             b0 + (wn + 32 + brow2) * ROWB + bcol2 * 16);
            }
#pragma unroll
            for (int mi = 0; mi < 2; mi++)
#pragma unroll
                for (int nj = 0; nj < 5; nj++)
                    mma_16816(acc[mi][nj], ah[mi], bh[2 * nj], bh[2 * nj + 1]);
        }

        if (more) CP_WAIT0();   // A/B(s+1) landed (a full MMA stage of slack)
        __syncthreads();        // buffer handoff
    }

    // ---- epilogue: bias + scatter ----
#pragma unroll
    for (int mi = 0; mi < 2; mi++) {
        const int ur0 = u0 + wm + mi * 16 + (lane >> 2);
#pragma unroll
        for (int half = 0; half < 2; half++) {
            const int ur = ur0 + half * 8;
            if (ur >= (HW << 4)) continue;
            const int img_e = ur >> (2 * logW);
            const int p_e   = ur & (HW - 1);
#pragma unroll
            for (int nj = 0; nj < 5; nj++) {
                const int o0 = wn + nj * 8 + (lane & 3) * 2;
                const float v0 = acc[mi][nj][half * 2];
                const float v1 = acc[mi][nj][half * 2 + 1];
                if (o0 < 78)     store_one(out, o0,     v0, img_e, off_l, HW, p_e, head);
                if (o0 + 1 < 78) store_one(out, o0 + 1, v1, img_e, off_l, HW, p_e, head);
            }
        }
    }
}

// ---------------------------------------------------------------------------
extern "C" void kernel_launch(void* const* d_in, const int* in_sizes, int n_in,
                              void* d_out, int out_size)
{
    cudaFuncSetAttribute(head_kernel, cudaFuncAttributeMaxDynamicSharedMemorySize, SMEM_TOTAL);

    transpose_kernel<<<1365, NTH>>>(
        (const float*)d_in[0], (const float*)d_in[1], (const float*)d_in[2],
        (const float*)d_in[3], (const float*)d_in[4], (const float*)d_in[5]);

    repack_kernel<<<(BPACK_ELEMS + NTH - 1) / NTH, NTH>>>(
        (const float*)d_in[6],  (const float*)d_in[7],
        (const float*)d_in[8],  (const float*)d_in[9],
        (const float*)d_in[10], (const float*)d_in[11],
        (const float*)d_in[12], (const float*)d_in[13]);

    head_kernel<<<683, NTH, SMEM_TOTAL>>>((float*)d_out);
}